// round 14
// baseline (speedup 1.0000x reference)
#include <cuda_runtime.h>
#include <cuda_fp16.h>
#include <cstdint>

// ---------------------------------------------------------------------------
// Problem constants
// ---------------------------------------------------------------------------
#define NB        128
#define TT        2048
#define FF        88
#define WIN       64
#define X_ELEMS   (NB*TT*FF)            // 23068672
#define W_ELEMS   (FF*WIN*FF)           // 495616
#define OUT_HALF  23068672              // elements per output copy
#define TILE_T    256                   // t rows per CTA
#define NWARPS    8
#define ROWS_PER_WARP 32                // 2 m16 tiles
#define WP2       368                   // pair-half image pitch (23 x 16B, odd -> conflict-free)
#define SLOT_BYTES 17664                // 48 rows x 368 (h0); h1 uses 40 rows = 14720
#define H1_BYTES  14720
#define XPITCH    176                   // 88 fp16 bytes per frame
#define WINFRAMES 319                   // 64 + 256 - 1 frames
#define NSLOTS    3

// smem layout
#define S_MBX     16
#define S_MBW     32                    // 3 x 8B mbarriers
#define S_W       1024                  // 3 slots x 17664
#define S_X       (1024 + NSLOTS*SLOT_BYTES)      // 54016
#define X_BYTES   (WINFRAMES*XPITCH)              // 56144
#define SMEM_ALLOC (S_X + X_BYTES + 64)           // 110224 (x2 CTAs fits 228KB/SM)

// ---------------------------------------------------------------------------
// Device scratch (static — no runtime allocation allowed)
// ---------------------------------------------------------------------------
__device__ __align__(1024) unsigned char g_Wimg[64 * SLOT_BYTES];   // 1.13 MB
__device__ __align__(16)   __half        g_xh[X_ELEMS];             // 46 MB

// ---------------------------------------------------------------------------
// PTX helpers (base features only — NO tcgen05/TMEM, target is plain sm_103)
// ---------------------------------------------------------------------------
__device__ __forceinline__ uint32_t smem_to_u32(const void* p) {
    uint32_t a;
    asm("{ .reg .u64 t; cvta.to.shared.u64 t, %1; cvt.u32.u64 %0, t; }" : "=r"(a) : "l"(p));
    return a;
}

#define MBARRIER_INIT(addr, cnt) \
    asm volatile("mbarrier.init.shared.b64 [%0], %1;" :: "r"((uint32_t)(addr)), "r"((uint32_t)(cnt)) : "memory")

#define MBARRIER_EXPECT_TX(addr, bytes) \
    asm volatile("mbarrier.arrive.expect_tx.shared.b64 _, [%0], %1;" :: "r"((uint32_t)(addr)), "r"((uint32_t)(bytes)) : "memory")

#define MBARRIER_WAIT_PARITY(mbar_smem_addr, phase_parity) do { \
    uint32_t _mbar = (uint32_t)(mbar_smem_addr); \
    uint32_t _parity = (uint32_t)(phase_parity); \
    uint32_t _done; \
    asm volatile("{\n\t.reg .pred p;\n\t" \
        "mbarrier.try_wait.parity.acquire.cta.shared::cta.b64 p, [%1], %2;\n\t" \
        "selp.b32 %0, 1, 0, p;\n\t}" \
        : "=r"(_done) : "r"(_mbar), "r"(_parity) : "memory"); \
    if (!_done) { \
        asm volatile("{\n\t.reg .pred P1;\n\t" \
            "WAIT_LOOP_%=:\n\t" \
            "mbarrier.try_wait.parity.acquire.cta.shared::cta.b64 P1, [%0], %1, 0x989680;\n\t" \
            "@P1 bra.uni WAIT_DONE_%=;\n\t" \
            "bra.uni WAIT_LOOP_%=;\n\t" \
            "WAIT_DONE_%=:\n\t}" \
            :: "r"(_mbar), "r"(_parity) : "memory"); \
    } \
} while(0)

__device__ __forceinline__ void bulk_g2s(uint32_t dst_smem, const void* src,
                                         uint32_t bytes, uint32_t mbar) {
    asm volatile(
        "cp.async.bulk.shared::cta.global.mbarrier::complete_tx::bytes [%0], [%1], %2, [%3];"
        :: "r"(dst_smem), "l"(src), "r"(bytes), "r"(mbar) : "memory");
}

__device__ __forceinline__ void ldmatrix_x4(uint32_t& r0, uint32_t& r1,
                                            uint32_t& r2, uint32_t& r3, uint32_t addr) {
    asm volatile("ldmatrix.sync.aligned.m8n8.x4.shared.b16 {%0,%1,%2,%3}, [%4];"
        : "=r"(r0), "=r"(r1), "=r"(r2), "=r"(r3) : "r"(addr));
}
__device__ __forceinline__ void ldmatrix_x2(uint32_t& r0, uint32_t& r1, uint32_t addr) {
    asm volatile("ldmatrix.sync.aligned.m8n8.x2.shared.b16 {%0,%1}, [%2];"
        : "=r"(r0), "=r"(r1) : "r"(addr));
}

__device__ __forceinline__ void mma16816(float* c, uint32_t a0, uint32_t a1,
                                         uint32_t a2, uint32_t a3,
                                         uint32_t b0, uint32_t b1) {
    asm volatile("mma.sync.aligned.m16n8k16.row.col.f32.f16.f16.f32 "
        "{%0,%1,%2,%3}, {%4,%5,%6,%7}, {%8,%9}, {%0,%1,%2,%3};"
        : "+f"(c[0]), "+f"(c[1]), "+f"(c[2]), "+f"(c[3])
        : "r"(a0), "r"(a1), "r"(a2), "r"(a3), "r"(b0), "r"(b1));
}

// ---------------------------------------------------------------------------
// Fused prep kernel (PROVEN structure from round 6/7):
// blocks [0,2048): x fp32 -> fp16 into g_xh
// blocks [2048,..): W -> per-(pair,half) images
//   q = pair*2 + h; image q rows r (n = 48h + r; 48 rows h0, 40 rows h1),
//   cols k2 = 0..175 (tau = 2*pair + k2/88, k = k2%88), pitch WP2.
// ---------------------------------------------------------------------------
#define PREP_X_BLOCKS 2048
#define PREP_W_ITEMS  (64*48*176)       // 540672
#define PREP_W_BLOCKS ((PREP_W_ITEMS + 255)/256)

__global__ void prep_kernel(const float* __restrict__ x, const float* __restrict__ W) {
    if (blockIdx.x < PREP_X_BLOCKS) {
        size_t i = (size_t)blockIdx.x * blockDim.x + threadIdx.x;
        size_t stride = (size_t)PREP_X_BLOCKS * blockDim.x;
        const float4* x4 = (const float4*)x;
        __half2* o = (__half2*)g_xh;
        size_t n4 = X_ELEMS / 4;
        for (; i < n4; i += stride) {
            float4 v = x4[i];
            o[2*i]   = __floats2half2_rn(v.x, v.y);
            o[2*i+1] = __floats2half2_rn(v.z, v.w);
        }
    } else {
        int idx = (blockIdx.x - PREP_X_BLOCKS) * 256 + threadIdx.x;
        if (idx >= PREP_W_ITEMS) return;
        int k2 = idx % 176;
        int r  = (idx / 176) % 48;
        int q  = idx / (176 * 48);
        int h  = q & 1, p = q >> 1;
        if (h && r >= 40) return;
        int n   = 48*h + r;
        int tau = 2*p + (k2 / 88);
        int k   = k2 % 88;
        float v = W[(size_t)n * (WIN*FF) + tau * FF + k];
        *(__half*)(g_Wimg + (size_t)q * SLOT_BYTES + (size_t)r * WP2 + (size_t)k2 * 2)
            = __float2half_rn(v);
    }
}

// ---------------------------------------------------------------------------
// Main kernel: 256 rows x 88 cols per CTA, 32 tau-pairs x 11 k16 steps, occ=2.
// x window bulk-copied from g_xh (proven); W streamed via 3-slot ring.
// ---------------------------------------------------------------------------
__global__ void __launch_bounds__(256, 2)
main_gemm_kernel(const float* __restrict__ bias, float* __restrict__ out) {
    extern __shared__ unsigned char smem[];
    uint32_t sb = smem_to_u32(smem);
    int tid = threadIdx.x;
    int wid = tid >> 5, lane = tid & 31;

    int cta = blockIdx.x;
    int n_b = cta >> 3;               // batch index
    int t0  = (cta & 7) * TILE_T;

    uint32_t mb_x = sb + S_MBX;
    uint32_t mb_w = sb + S_MBW;       // 3 barriers

    if (tid == 0) {
        MBARRIER_INIT(mb_x, 1);
        MBARRIER_INIT(mb_w + 0, 1);
        MBARRIER_INIT(mb_w + 8, 1);
        MBARRIER_INIT(mb_w + 16, 1);
    }
    // zero-pad the first 64 frames when t0 == 0
    if (t0 == 0) {
        for (int i = tid; i < WIN*XPITCH/4; i += 256)
            *(uint32_t*)(smem + S_X + i*4) = 0u;
    }
    __syncthreads();

    if (tid == 0) {
        if (t0 == 0) {
            MBARRIER_EXPECT_TX(mb_x, (WINFRAMES-WIN)*XPITCH);
            bulk_g2s(sb + S_X + WIN*XPITCH,
                     (const void*)(g_xh + (size_t)n_b*TT*FF),
                     (WINFRAMES-WIN)*XPITCH, mb_x);
        } else {
            MBARRIER_EXPECT_TX(mb_x, WINFRAMES*XPITCH);
            bulk_g2s(sb + S_X,
                     (const void*)(g_xh + ((size_t)n_b*TT + t0 - WIN)*FF),
                     WINFRAMES*XPITCH, mb_x);
        }
        #pragma unroll
        for (int q = 0; q < NSLOTS; q++) {
            uint32_t bytes = (q & 1) ? H1_BYTES : SLOT_BYTES;
            MBARRIER_EXPECT_TX(mb_w + q*8, bytes);
            bulk_g2s(sb + S_W + q*SLOT_BYTES,
                     (const void*)(g_Wimg + (size_t)q*SLOT_BYTES), bytes, mb_w + q*8);
        }
    }
    MBARRIER_WAIT_PARITY(mb_x, 0);

    // per-lane base addresses
    // A: rows (lane&15) within warp's 32-row block; 16B-half select by lane>>4
    uint32_t a_base = sb + S_X
        + (uint32_t)(wid*ROWS_PER_WARP + (lane & 15)) * XPITCH
        + ((uint32_t)(lane >> 4) << 4);
    // B x4: local rows (lane&7) + 8*((lane>>4)&1) (+ jp*16), 16B col (lane>>3)&1
    uint32_t b_lane = (uint32_t)((lane & 7) + ((lane >> 4) & 1) * 8) * WP2
        + (uint32_t)((lane >> 3) & 1) * 16;
    // B x2 (h1, local rows 32..39)
    uint32_t b_lane2 = (uint32_t)(32 + (lane & 7)) * WP2
        + (uint32_t)((lane >> 3) & 1) * 16;

    float acc[2][11][4];
    #pragma unroll
    for (int mt = 0; mt < 2; mt++)
        #pragma unroll
        for (int j = 0; j < 11; j++)
            #pragma unroll
            for (int c = 0; c < 4; c++) acc[mt][j][c] = 0.0f;

    int slot = 0;
    uint32_t wpar = 0;   // per-slot next-wait parity bits

    for (int q = 0; q < 64; q++) {
        int h = q & 1, p = q >> 1;
        MBARRIER_WAIT_PARITY(mb_w + slot*8, (wpar >> slot) & 1);

        uint32_t wbase = sb + S_W + (uint32_t)slot * SLOT_BYTES;
        uint32_t abase_p = a_base + (uint32_t)p * (2*XPITCH);

        if (h == 0) {
            // n-tiles 0..5 (48 rows), 11 k16 steps
            #pragma unroll
            for (int kk = 0; kk < 11; kk++) {
                uint32_t a0[4], a1[4];
                ldmatrix_x4(a0[0], a0[1], a0[2], a0[3], abase_p + kk*32);
                ldmatrix_x4(a1[0], a1[1], a1[2], a1[3], abase_p + 16*XPITCH + kk*32);
                #pragma unroll
                for (int jp = 0; jp < 3; jp++) {
                    uint32_t b0, b1, b2, b3;
                    ldmatrix_x4(b0, b1, b2, b3, wbase + b_lane + (uint32_t)jp*16*WP2 + kk*32);
                    mma16816(acc[0][2*jp],   a0[0], a0[1], a0[2], a0[3], b0, b1);
                    mma16816(acc[1][2*jp],   a1[0], a1[1], a1[2], a1[3], b0, b1);
                    mma16816(acc[0][2*jp+1], a0[0], a0[1], a0[2], a0[3], b2, b3);
                    mma16816(acc[1][2*jp+1], a1[0], a1[1], a1[2], a1[3], b2, b3);
                }
            }
        } else {
            // n-tiles 6..10 (40 rows), 11 k16 steps
            #pragma unroll
            for (int kk = 0; kk < 11; kk++) {
                uint32_t a0[4], a1[4];
                ldmatrix_x4(a0[0], a0[1], a0[2], a0[3], abase_p + kk*32);
                ldmatrix_x4(a1[0], a1[1], a1[2], a1[3], abase_p + 16*XPITCH + kk*32);
                #pragma unroll
                for (int jp = 0; jp < 2; jp++) {
                    uint32_t b0, b1, b2, b3;
                    ldmatrix_x4(b0, b1, b2, b3, wbase + b_lane + (uint32_t)jp*16*WP2 + kk*32);
                    mma16816(acc[0][6+2*jp], a0[0], a0[1], a0[2], a0[3], b0, b1);
                    mma16816(acc[1][6+2*jp], a1[0], a1[1], a1[2], a1[3], b0, b1);
                    mma16816(acc[0][7+2*jp], a0[0], a0[1], a0[2], a0[3], b2, b3);
                    mma16816(acc[1][7+2*jp], a1[0], a1[1], a1[2], a1[3], b2, b3);
                }
                {
                    uint32_t b0, b1;
                    ldmatrix_x2(b0, b1, wbase + b_lane2 + kk*32);
                    mma16816(acc[0][10], a0[0], a0[1], a0[2], a0[3], b0, b1);
                    mma16816(acc[1][10], a1[0], a1[1], a1[2], a1[3], b0, b1);
                }
            }
        }

        __syncthreads();
        // reload SAME slot for q+3
        if (tid == 0 && q + NSLOTS < 64) {
            int qq = q + NSLOTS;
            uint32_t bytes = (qq & 1) ? H1_BYTES : SLOT_BYTES;
            MBARRIER_EXPECT_TX(mb_w + slot*8, bytes);
            bulk_g2s(sb + S_W + (uint32_t)slot*SLOT_BYTES,
                     (const void*)(g_Wimg + (size_t)qq*SLOT_BYTES), bytes, mb_w + slot*8);
        }
        wpar ^= (1u << slot);
        slot = (slot == NSLOTS-1) ? 0 : slot + 1;
    }

    // ---- epilogue: add bias, store twice ----
    {
        int col0 = (lane & 3) * 2;          // within n-tile
        int rbase = t0 + wid * ROWS_PER_WARP + (lane >> 2);
        #pragma unroll
        for (int mt = 0; mt < 2; mt++) {
            int r0 = rbase + mt * 16;
            size_t g0 = ((size_t)n_b * TT + r0)     * FF;
            size_t g1 = ((size_t)n_b * TT + r0 + 8) * FF;
            #pragma unroll
            for (int j = 0; j < 11; j++) {
                int c = j * 8 + col0;
                float bx = bias[c], by = bias[c + 1];
                float2 v0 = make_float2(acc[mt][j][0] + bx, acc[mt][j][1] + by);
                float2 v1 = make_float2(acc[mt][j][2] + bx, acc[mt][j][3] + by);
                *(float2*)(out + g0 + c) = v0;
                *(float2*)(out + g1 + c) = v1;
                *(float2*)(out + OUT_HALF + g0 + c) = v0;
                *(float2*)(out + OUT_HALF + g1 + c) = v1;
            }
        }
    }
}

// ---------------------------------------------------------------------------
// Launch
// ---------------------------------------------------------------------------
extern "C" void kernel_launch(void* const* d_in, const int* in_sizes, int n_in,
                              void* d_out, int out_size) {
    const float *x = nullptr, *W = nullptr, *b = nullptr;
    for (int i = 0; i < n_in; i++) {
        if      (in_sizes[i] == X_ELEMS) x = (const float*)d_in[i];
        else if (in_sizes[i] == W_ELEMS) W = (const float*)d_in[i];
        else if (in_sizes[i] == FF)      b = (const float*)d_in[i];
    }
    cudaFuncSetAttribute(main_gemm_kernel,
                         cudaFuncAttributeMaxDynamicSharedMemorySize, SMEM_ALLOC);
    prep_kernel<<<PREP_X_BLOCKS + PREP_W_BLOCKS, 256>>>(x, W);
    main_gemm_kernel<<<NB*(TT/TILE_T), 256, SMEM_ALLOC>>>(b, (float*)d_out);
}

// round 15
// speedup vs baseline: 1.0715x; 1.0715x over previous
#include <cuda_runtime.h>
#include <cuda_fp16.h>
#include <cstdint>

// ---------------------------------------------------------------------------
// Problem constants
// ---------------------------------------------------------------------------
#define NB        128
#define TT        2048
#define FF        88
#define WIN       64
#define X_ELEMS   (NB*TT*FF)            // 23068672
#define W_ELEMS   (FF*WIN*FF)           // 495616
#define OUT_HALF  23068672              // elements per output copy
#define TILE_T    256                   // t rows per CTA
#define NWARPS    8
#define ROWS_PER_WARP 32                // 2 m16 tiles
#define WP2       368                   // pair-half image pitch (23 x 16B, odd -> conflict-free)
#define SLOT_BYTES 17664                // 48 rows x 368 (h0); h1 uses 40 rows = 14720
#define H1_BYTES  14720
#define XPITCH    176                   // 88 fp16 bytes per frame
#define WINFRAMES 319                   // 64 + 256 - 1 frames
#define NSLOTS    3

// smem layout
#define S_MBX     16
#define S_MBW     32                    // 3 x 8B mbarriers
#define S_W       1024                  // 3 slots x 17664
#define S_X       (1024 + NSLOTS*SLOT_BYTES)      // 54016
#define X_BYTES   (WINFRAMES*XPITCH)              // 56144
#define SMEM_ALLOC (S_X + X_BYTES + 64)           // 110224 (x2 CTAs fits 228KB/SM)

// ---------------------------------------------------------------------------
// Device scratch (static — no runtime allocation allowed)
// ---------------------------------------------------------------------------
__device__ __align__(1024) unsigned char g_Wimg[64 * SLOT_BYTES];   // 1.13 MB
__device__ __align__(16)   __half        g_xh[X_ELEMS];             // 46 MB

// ---------------------------------------------------------------------------
// PTX helpers (base features only — NO tcgen05/TMEM, target is plain sm_103)
// ---------------------------------------------------------------------------
__device__ __forceinline__ uint32_t smem_to_u32(const void* p) {
    uint32_t a;
    asm("{ .reg .u64 t; cvta.to.shared.u64 t, %1; cvt.u32.u64 %0, t; }" : "=r"(a) : "l"(p));
    return a;
}

#define MBARRIER_INIT(addr, cnt) \
    asm volatile("mbarrier.init.shared.b64 [%0], %1;" :: "r"((uint32_t)(addr)), "r"((uint32_t)(cnt)) : "memory")

#define MBARRIER_EXPECT_TX(addr, bytes) \
    asm volatile("mbarrier.arrive.expect_tx.shared.b64 _, [%0], %1;" :: "r"((uint32_t)(addr)), "r"((uint32_t)(bytes)) : "memory")

#define MBARRIER_WAIT_PARITY(mbar_smem_addr, phase_parity) do { \
    uint32_t _mbar = (uint32_t)(mbar_smem_addr); \
    uint32_t _parity = (uint32_t)(phase_parity); \
    uint32_t _done; \
    asm volatile("{\n\t.reg .pred p;\n\t" \
        "mbarrier.try_wait.parity.acquire.cta.shared::cta.b64 p, [%1], %2;\n\t" \
        "selp.b32 %0, 1, 0, p;\n\t}" \
        : "=r"(_done) : "r"(_mbar), "r"(_parity) : "memory"); \
    if (!_done) { \
        asm volatile("{\n\t.reg .pred P1;\n\t" \
            "WAIT_LOOP_%=:\n\t" \
            "mbarrier.try_wait.parity.acquire.cta.shared::cta.b64 P1, [%0], %1, 0x989680;\n\t" \
            "@P1 bra.uni WAIT_DONE_%=;\n\t" \
            "bra.uni WAIT_LOOP_%=;\n\t" \
            "WAIT_DONE_%=:\n\t}" \
            :: "r"(_mbar), "r"(_parity) : "memory"); \
    } \
} while(0)

__device__ __forceinline__ void bulk_g2s(uint32_t dst_smem, const void* src,
                                         uint32_t bytes, uint32_t mbar) {
    asm volatile(
        "cp.async.bulk.shared::cta.global.mbarrier::complete_tx::bytes [%0], [%1], %2, [%3];"
        :: "r"(dst_smem), "l"(src), "r"(bytes), "r"(mbar) : "memory");
}

__device__ __forceinline__ void ldmatrix_x4(uint32_t& r0, uint32_t& r1,
                                            uint32_t& r2, uint32_t& r3, uint32_t addr) {
    asm volatile("ldmatrix.sync.aligned.m8n8.x4.shared.b16 {%0,%1,%2,%3}, [%4];"
        : "=r"(r0), "=r"(r1), "=r"(r2), "=r"(r3) : "r"(addr));
}
__device__ __forceinline__ void ldmatrix_x2(uint32_t& r0, uint32_t& r1, uint32_t addr) {
    asm volatile("ldmatrix.sync.aligned.m8n8.x2.shared.b16 {%0,%1}, [%2];"
        : "=r"(r0), "=r"(r1) : "r"(addr));
}

__device__ __forceinline__ void mma16816(float* c, uint32_t a0, uint32_t a1,
                                         uint32_t a2, uint32_t a3,
                                         uint32_t b0, uint32_t b1) {
    asm volatile("mma.sync.aligned.m16n8k16.row.col.f32.f16.f16.f32 "
        "{%0,%1,%2,%3}, {%4,%5,%6,%7}, {%8,%9}, {%0,%1,%2,%3};"
        : "+f"(c[0]), "+f"(c[1]), "+f"(c[2]), "+f"(c[3])
        : "r"(a0), "r"(a1), "r"(a2), "r"(a3), "r"(b0), "r"(b1));
}

// ---------------------------------------------------------------------------
// Fused prep kernel:
// blocks [0,2048): x fp32 -> fp16 into g_xh
// blocks [2048,..): W -> per-(pair,half) images
//   q = pair*2 + h; image q rows r (n = 48h + r; 48 rows h0, 40 rows h1),
//   cols k2 = 0..175 (tau = 2*pair + k2/88, k = k2%88), pitch WP2.
// ---------------------------------------------------------------------------
#define PREP_X_BLOCKS 2048
#define PREP_W_ITEMS  (64*48*176)       // 540672
#define PREP_W_BLOCKS ((PREP_W_ITEMS + 255)/256)

__global__ void prep_kernel(const float* __restrict__ x, const float* __restrict__ W) {
    if (blockIdx.x < PREP_X_BLOCKS) {
        size_t i = (size_t)blockIdx.x * blockDim.x + threadIdx.x;
        size_t stride = (size_t)PREP_X_BLOCKS * blockDim.x;
        const float4* x4 = (const float4*)x;
        __half2* o = (__half2*)g_xh;
        size_t n4 = X_ELEMS / 4;
        for (; i < n4; i += stride) {
            float4 v = x4[i];
            o[2*i]   = __floats2half2_rn(v.x, v.y);
            o[2*i+1] = __floats2half2_rn(v.z, v.w);
        }
    } else {
        int idx = (blockIdx.x - PREP_X_BLOCKS) * 256 + threadIdx.x;
        if (idx >= PREP_W_ITEMS) return;
        int k2 = idx % 176;
        int r  = (idx / 176) % 48;
        int q  = idx / (176 * 48);
        int h  = q & 1, p = q >> 1;
        if (h && r >= 40) return;
        int n   = 48*h + r;
        int tau = 2*p + (k2 / 88);
        int k   = k2 % 88;
        float v = W[(size_t)n * (WIN*FF) + tau * FF + k];
        *(__half*)(g_Wimg + (size_t)q * SLOT_BYTES + (size_t)r * WP2 + (size_t)k2 * 2)
            = __float2half_rn(v);
    }
}

// ---------------------------------------------------------------------------
// Main kernel: 256 rows x 88 cols per CTA, 32 tau-pairs, occ=2.
// Both halves of a pair processed per k-step over SHARED A fragments
// (A ldmatrix halved vs per-half loop). 3-slot W ring, slots advance +2 mod 3.
// ---------------------------------------------------------------------------
__global__ void __launch_bounds__(256, 2)
main_gemm_kernel(const float* __restrict__ bias, float* __restrict__ out) {
    extern __shared__ unsigned char smem[];
    uint32_t sb = smem_to_u32(smem);
    int tid = threadIdx.x;
    int wid = tid >> 5, lane = tid & 31;

    int cta = blockIdx.x;
    int n_b = cta >> 3;               // batch index
    int t0  = (cta & 7) * TILE_T;

    uint32_t mb_x = sb + S_MBX;
    uint32_t mb_w = sb + S_MBW;       // 3 barriers

    if (tid == 0) {
        MBARRIER_INIT(mb_x, 1);
        MBARRIER_INIT(mb_w + 0, 1);
        MBARRIER_INIT(mb_w + 8, 1);
        MBARRIER_INIT(mb_w + 16, 1);
    }
    // zero-pad the first 64 frames when t0 == 0
    if (t0 == 0) {
        for (int i = tid; i < WIN*XPITCH/4; i += 256)
            *(uint32_t*)(smem + S_X + i*4) = 0u;
    }
    __syncthreads();

    if (tid == 0) {
        if (t0 == 0) {
            MBARRIER_EXPECT_TX(mb_x, (WINFRAMES-WIN)*XPITCH);
            bulk_g2s(sb + S_X + WIN*XPITCH,
                     (const void*)(g_xh + (size_t)n_b*TT*FF),
                     (WINFRAMES-WIN)*XPITCH, mb_x);
        } else {
            MBARRIER_EXPECT_TX(mb_x, WINFRAMES*XPITCH);
            bulk_g2s(sb + S_X,
                     (const void*)(g_xh + ((size_t)n_b*TT + t0 - WIN)*FF),
                     WINFRAMES*XPITCH, mb_x);
        }
        #pragma unroll
        for (int q = 0; q < NSLOTS; q++) {
            uint32_t bytes = (q & 1) ? H1_BYTES : SLOT_BYTES;
            MBARRIER_EXPECT_TX(mb_w + q*8, bytes);
            bulk_g2s(sb + S_W + q*SLOT_BYTES,
                     (const void*)(g_Wimg + (size_t)q*SLOT_BYTES), bytes, mb_w + q*8);
        }
    }
    MBARRIER_WAIT_PARITY(mb_x, 0);

    // per-lane base addresses
    // A: rows (lane&15) within warp's 32-row block; 16B-half select by lane>>4
    uint32_t a_base = sb + S_X
        + (uint32_t)(wid*ROWS_PER_WARP + (lane & 15)) * XPITCH
        + ((uint32_t)(lane >> 4) << 4);
    // B x4: local rows (lane&7) + 8*((lane>>4)&1) (+ jp*16), 16B col (lane>>3)&1
    uint32_t b_lane = (uint32_t)((lane & 7) + ((lane >> 4) & 1) * 8) * WP2
        + (uint32_t)((lane >> 3) & 1) * 16;
    // B x2 (h1 image, local rows 32..39)
    uint32_t b_lane2 = (uint32_t)(32 + (lane & 7)) * WP2
        + (uint32_t)((lane >> 3) & 1) * 16;

    float acc[2][11][4];
    #pragma unroll
    for (int mt = 0; mt < 2; mt++)
        #pragma unroll
        for (int j = 0; j < 11; j++)
            #pragma unroll
            for (int c = 0; c < 4; c++) acc[mt][j][c] = 0.0f;

    int slot = 0;        // slot holding q = 2p (h0 image); (slot+1)%3 holds q = 2p+1
    uint32_t wpar = 0;   // per-slot next-wait parity bits

    for (int p = 0; p < 32; p++) {
        int s0 = slot;
        int s1 = (slot + 1 == NSLOTS) ? 0 : slot + 1;
        MBARRIER_WAIT_PARITY(mb_w + s0*8, (wpar >> s0) & 1);
        MBARRIER_WAIT_PARITY(mb_w + s1*8, (wpar >> s1) & 1);

        uint32_t w0 = sb + S_W + (uint32_t)s0 * SLOT_BYTES;   // h0: n 0..47
        uint32_t w1 = sb + S_W + (uint32_t)s1 * SLOT_BYTES;   // h1: n 48..87
        uint32_t abase_p = a_base + (uint32_t)p * (2*XPITCH);

        #pragma unroll
        for (int kk = 0; kk < 11; kk++) {
            uint32_t a0[4], a1[4];
            ldmatrix_x4(a0[0], a0[1], a0[2], a0[3], abase_p + kk*32);
            ldmatrix_x4(a1[0], a1[1], a1[2], a1[3], abase_p + 16*XPITCH + kk*32);
            // h0: n-tiles 0..5
            #pragma unroll
            for (int jp = 0; jp < 3; jp++) {
                uint32_t b0, b1, b2, b3;
                ldmatrix_x4(b0, b1, b2, b3, w0 + b_lane + (uint32_t)jp*16*WP2 + kk*32);
                mma16816(acc[0][2*jp],   a0[0], a0[1], a0[2], a0[3], b0, b1);
                mma16816(acc[1][2*jp],   a1[0], a1[1], a1[2], a1[3], b0, b1);
                mma16816(acc[0][2*jp+1], a0[0], a0[1], a0[2], a0[3], b2, b3);
                mma16816(acc[1][2*jp+1], a1[0], a1[1], a1[2], a1[3], b2, b3);
            }
            // h1: n-tiles 6..9
            #pragma unroll
            for (int jp = 0; jp < 2; jp++) {
                uint32_t b0, b1, b2, b3;
                ldmatrix_x4(b0, b1, b2, b3, w1 + b_lane + (uint32_t)jp*16*WP2 + kk*32);
                mma16816(acc[0][6+2*jp], a0[0], a0[1], a0[2], a0[3], b0, b1);
                mma16816(acc[1][6+2*jp], a1[0], a1[1], a1[2], a1[3], b0, b1);
                mma16816(acc[0][7+2*jp], a0[0], a0[1], a0[2], a0[3], b2, b3);
                mma16816(acc[1][7+2*jp], a1[0], a1[1], a1[2], a1[3], b2, b3);
            }
            // h1: n-tile 10
            {
                uint32_t b0, b1;
                ldmatrix_x2(b0, b1, w1 + b_lane2 + kk*32);
                mma16816(acc[0][10], a0[0], a0[1], a0[2], a0[3], b0, b1);
                mma16816(acc[1][10], a1[0], a1[1], a1[2], a1[3], b0, b1);
            }
        }

        __syncthreads();
        // reload: s0 <- q=2p+3 (odd, H1 bytes), s1 <- q=2p+4 (even, full bytes)
        if (tid == 0) {
            int qa = 2*p + 3;
            if (qa < 64) {
                MBARRIER_EXPECT_TX(mb_w + s0*8, H1_BYTES);
                bulk_g2s(sb + S_W + (uint32_t)s0*SLOT_BYTES,
                         (const void*)(g_Wimg + (size_t)qa*SLOT_BYTES), H1_BYTES, mb_w + s0*8);
            }
            int qb = 2*p + 4;
            if (qb < 64) {
                MBARRIER_EXPECT_TX(mb_w + s1*8, SLOT_BYTES);
                bulk_g2s(sb + S_W + (uint32_t)s1*SLOT_BYTES,
                         (const void*)(g_Wimg + (size_t)qb*SLOT_BYTES), SLOT_BYTES, mb_w + s1*8);
            }
        }
        wpar ^= (1u << s0);
        wpar ^= (1u << s1);
        slot = (slot + 2 >= NSLOTS) ? slot + 2 - NSLOTS : slot + 2;
    }

    // ---- epilogue: add bias, store twice ----
    {
        int col0 = (lane & 3) * 2;          // within n-tile
        int rbase = t0 + wid * ROWS_PER_WARP + (lane >> 2);
        #pragma unroll
        for (int mt = 0; mt < 2; mt++) {
            int r0 = rbase + mt * 16;
            size_t g0 = ((size_t)n_b * TT + r0)     * FF;
            size_t g1 = ((size_t)n_b * TT + r0 + 8) * FF;
            #pragma unroll
            for (int j = 0; j < 11; j++) {
                int c = j * 8 + col0;
                float bx = bias[c], by = bias[c + 1];
                float2 v0 = make_float2(acc[mt][j][0] + bx, acc[mt][j][1] + by);
                float2 v1 = make_float2(acc[mt][j][2] + bx, acc[mt][j][3] + by);
                *(float2*)(out + g0 + c) = v0;
                *(float2*)(out + g1 + c) = v1;
                *(float2*)(out + OUT_HALF + g0 + c) = v0;
                *(float2*)(out + OUT_HALF + g1 + c) = v1;
            }
        }
    }
}

// ---------------------------------------------------------------------------
// Launch
// ---------------------------------------------------------------------------
extern "C" void kernel_launch(void* const* d_in, const int* in_sizes, int n_in,
                              void* d_out, int out_size) {
    const float *x = nullptr, *W = nullptr, *b = nullptr;
    for (int i = 0; i < n_in; i++) {
        if      (in_sizes[i] == X_ELEMS) x = (const float*)d_in[i];
        else if (in_sizes[i] == W_ELEMS) W = (const float*)d_in[i];
        else if (in_sizes[i] == FF)      b = (const float*)d_in[i];
    }
    cudaFuncSetAttribute(main_gemm_kernel,
                         cudaFuncAttributeMaxDynamicSharedMemorySize, SMEM_ALLOC);
    prep_kernel<<<PREP_X_BLOCKS + PREP_W_BLOCKS, 256>>>(x, W);
    main_gemm_kernel<<<NB*(TT/TILE_T), 256, SMEM_ALLOC>>>(b, (float*)d_out);
}

// round 16
// speedup vs baseline: 1.0862x; 1.0137x over previous
#include <cuda_runtime.h>
#include <cuda_fp16.h>
#include <cstdint>

// ---------------------------------------------------------------------------
// Problem constants
// ---------------------------------------------------------------------------
#define NB        128
#define TT        2048
#define FF        88
#define WIN       64
#define X_ELEMS   (NB*TT*FF)            // 23068672
#define W_ELEMS   (FF*WIN*FF)           // 495616
#define OUT_HALF  23068672              // elements per output copy
#define TILE_T    256                   // t rows per CTA
#define NWARPS    8
#define ROWS_PER_WARP 32                // 2 m16 tiles
#define WP2       368                   // pair-half image pitch (23 x 16B, odd -> conflict-free)
#define SLOT_BYTES 17664                // 48 rows x 368 (h0); h1 uses 40 rows = 14720
#define H1_BYTES  14720
#define XPITCH    176                   // 88 fp16 bytes per frame
#define WINFRAMES 319                   // 64 + 256 - 1 frames
#define NSLOTS    3

// smem layout
#define S_MBW     32                    // 3 x 8B mbarriers
#define S_W       1024                  // 3 slots x 17664
#define S_X       (1024 + NSLOTS*SLOT_BYTES)      // 54016
#define X_BYTES   (WINFRAMES*XPITCH)              // 56144
#define SMEM_ALLOC (S_X + X_BYTES + 64)           // 110224 (x2 CTAs fits 228KB/SM)

// ---------------------------------------------------------------------------
// Device scratch (static — no runtime allocation allowed)
// ---------------------------------------------------------------------------
__device__ __align__(1024) unsigned char g_Wimg[64 * SLOT_BYTES];   // 1.13 MB

// ---------------------------------------------------------------------------
// PTX helpers (base features only — NO tcgen05/TMEM, target is plain sm_103)
// ---------------------------------------------------------------------------
__device__ __forceinline__ uint32_t smem_to_u32(const void* p) {
    uint32_t a;
    asm("{ .reg .u64 t; cvta.to.shared.u64 t, %1; cvt.u32.u64 %0, t; }" : "=r"(a) : "l"(p));
    return a;
}

#define MBARRIER_INIT(addr, cnt) \
    asm volatile("mbarrier.init.shared.b64 [%0], %1;" :: "r"((uint32_t)(addr)), "r"((uint32_t)(cnt)) : "memory")

#define MBARRIER_EXPECT_TX(addr, bytes) \
    asm volatile("mbarrier.arrive.expect_tx.shared.b64 _, [%0], %1;" :: "r"((uint32_t)(addr)), "r"((uint32_t)(bytes)) : "memory")

#define MBARRIER_WAIT_PARITY(mbar_smem_addr, phase_parity) do { \
    uint32_t _mbar = (uint32_t)(mbar_smem_addr); \
    uint32_t _parity = (uint32_t)(phase_parity); \
    uint32_t _done; \
    asm volatile("{\n\t.reg .pred p;\n\t" \
        "mbarrier.try_wait.parity.acquire.cta.shared::cta.b64 p, [%1], %2;\n\t" \
        "selp.b32 %0, 1, 0, p;\n\t}" \
        : "=r"(_done) : "r"(_mbar), "r"(_parity) : "memory"); \
    if (!_done) { \
        asm volatile("{\n\t.reg .pred P1;\n\t" \
            "WAIT_LOOP_%=:\n\t" \
            "mbarrier.try_wait.parity.acquire.cta.shared::cta.b64 P1, [%0], %1, 0x989680;\n\t" \
            "@P1 bra.uni WAIT_DONE_%=;\n\t" \
            "bra.uni WAIT_LOOP_%=;\n\t" \
            "WAIT_DONE_%=:\n\t}" \
            :: "r"(_mbar), "r"(_parity) : "memory"); \
    } \
} while(0)

__device__ __forceinline__ void bulk_g2s(uint32_t dst_smem, const void* src,
                                         uint32_t bytes, uint32_t mbar) {
    asm volatile(
        "cp.async.bulk.shared::cta.global.mbarrier::complete_tx::bytes [%0], [%1], %2, [%3];"
        :: "r"(dst_smem), "l"(src), "r"(bytes), "r"(mbar) : "memory");
}

__device__ __forceinline__ void ldmatrix_x4(uint32_t& r0, uint32_t& r1,
                                            uint32_t& r2, uint32_t& r3, uint32_t addr) {
    asm volatile("ldmatrix.sync.aligned.m8n8.x4.shared.b16 {%0,%1,%2,%3}, [%4];"
        : "=r"(r0), "=r"(r1), "=r"(r2), "=r"(r3) : "r"(addr));
}
__device__ __forceinline__ void ldmatrix_x2(uint32_t& r0, uint32_t& r1, uint32_t addr) {
    asm volatile("ldmatrix.sync.aligned.m8n8.x2.shared.b16 {%0,%1}, [%2];"
        : "=r"(r0), "=r"(r1) : "r"(addr));
}

__device__ __forceinline__ void mma16816(float* c, uint32_t a0, uint32_t a1,
                                         uint32_t a2, uint32_t a3,
                                         uint32_t b0, uint32_t b1) {
    asm volatile("mma.sync.aligned.m16n8k16.row.col.f32.f16.f16.f32 "
        "{%0,%1,%2,%3}, {%4,%5,%6,%7}, {%8,%9}, {%0,%1,%2,%3};"
        : "+f"(c[0]), "+f"(c[1]), "+f"(c[2]), "+f"(c[3])
        : "r"(a0), "r"(a1), "r"(a2), "r"(a3), "r"(b0), "r"(b1));
}

// ---------------------------------------------------------------------------
// W prep kernel: W -> per-(pair,half) images
//   q = pair*2 + h; image q rows r (n = 48h + r; 48 rows h0, 40 rows h1),
//   cols k2 = 0..175 (tau = 2*pair + k2/88, k = k2%88), pitch WP2.
// ---------------------------------------------------------------------------
#define PREP_W_ITEMS  (64*48*176)       // 540672
__global__ void prep_w_kernel(const float* __restrict__ W) {
    int idx = blockIdx.x * 256 + threadIdx.x;
    if (idx >= PREP_W_ITEMS) return;
    int k2 = idx % 176;
    int r  = (idx / 176) % 48;
    int q  = idx / (176 * 48);
    int h  = q & 1, p = q >> 1;
    if (h && r >= 40) return;
    int n   = 48*h + r;
    int tau = 2*p + (k2 / 88);
    int k   = k2 % 88;
    float v = W[(size_t)n * (WIN*FF) + tau * FF + k];
    *(__half*)(g_Wimg + (size_t)q * SLOT_BYTES + (size_t)r * WP2 + (size_t)k2 * 2)
        = __float2half_rn(v);
}

// ---------------------------------------------------------------------------
// Main kernel: 256 rows x 88 cols per CTA, 32 tau-pairs, occ=2.
// x fp32 -> fp16 converted in-kernel into the smem window (W prefetch overlaps).
// Both halves of a pair processed per k-step over SHARED A fragments.
// 3-slot W ring, slots advance +2 mod 3.
// ---------------------------------------------------------------------------
__global__ void __launch_bounds__(256, 2)
main_gemm_kernel(const float* __restrict__ x, const float* __restrict__ bias,
                 float* __restrict__ out) {
    extern __shared__ unsigned char smem[];
    uint32_t sb = smem_to_u32(smem);
    int tid = threadIdx.x;
    int wid = tid >> 5, lane = tid & 31;

    int cta = blockIdx.x;
    int n_b = cta >> 3;               // batch index
    int t0  = (cta & 7) * TILE_T;

    uint32_t mb_w = sb + S_MBW;       // 3 barriers

    if (tid == 0) {
        MBARRIER_INIT(mb_w + 0, 1);
        MBARRIER_INIT(mb_w + 8, 1);
        MBARRIER_INIT(mb_w + 16, 1);
    }
    __syncthreads();

    // kick W prefetch for q = 0,1,2 first (TMA overlaps the x conversion below)
    if (tid == 0) {
        #pragma unroll
        for (int q = 0; q < NSLOTS; q++) {
            uint32_t bytes = (q & 1) ? H1_BYTES : SLOT_BYTES;
            MBARRIER_EXPECT_TX(mb_w + q*8, bytes);
            bulk_g2s(sb + S_W + q*SLOT_BYTES,
                     (const void*)(g_Wimg + (size_t)q*SLOT_BYTES), bytes, mb_w + q*8);
        }
    }

    // ---- fused x conversion: fp32 gmem -> fp16 smem window (319 frames) ----
    {
        const float* xsrc = x + ((size_t)n_b*TT + t0 - WIN) * FF;  // frame f at xsrc + f*88
        int zlim = (t0 == 0) ? WIN : 0;
        for (int i = tid; i < WINFRAMES*22; i += 256) {
            int f = i / 22, c = i - f*22;           // 22 float4 per frame
            float4 v;
            if (f < zlim) v = make_float4(0.f, 0.f, 0.f, 0.f);
            else          v = *(const float4*)(xsrc + (size_t)f*FF + c*4);
            __half2 h0 = __floats2half2_rn(v.x, v.y);
            __half2 h1 = __floats2half2_rn(v.z, v.w);
            *(__half2*)(smem + S_X + f*XPITCH + c*8)     = h0;
            *(__half2*)(smem + S_X + f*XPITCH + c*8 + 4) = h1;
        }
    }
    __syncthreads();

    // per-lane base addresses
    // A: rows (lane&15) within warp's 32-row block; 16B-half select by lane>>4
    uint32_t a_base = sb + S_X
        + (uint32_t)(wid*ROWS_PER_WARP + (lane & 15)) * XPITCH
        + ((uint32_t)(lane >> 4) << 4);
    // B x4: local rows (lane&7) + 8*((lane>>4)&1) (+ jp*16), 16B col (lane>>3)&1
    uint32_t b_lane = (uint32_t)((lane & 7) + ((lane >> 4) & 1) * 8) * WP2
        + (uint32_t)((lane >> 3) & 1) * 16;
    // B x2 (h1 image, local rows 32..39)
    uint32_t b_lane2 = (uint32_t)(32 + (lane & 7)) * WP2
        + (uint32_t)((lane >> 3) & 1) * 16;

    float acc[2][11][4];
    #pragma unroll
    for (int mt = 0; mt < 2; mt++)
        #pragma unroll
        for (int j = 0; j < 11; j++)
            #pragma unroll
            for (int c = 0; c < 4; c++) acc[mt][j][c] = 0.0f;

    int slot = 0;        // slot holding q = 2p (h0 image); (slot+1)%3 holds q = 2p+1
    uint32_t wpar = 0;   // per-slot next-wait parity bits

    for (int p = 0; p < 32; p++) {
        int s0 = slot;
        int s1 = (slot + 1 == NSLOTS) ? 0 : slot + 1;
        MBARRIER_WAIT_PARITY(mb_w + s0*8, (wpar >> s0) & 1);
        MBARRIER_WAIT_PARITY(mb_w + s1*8, (wpar >> s1) & 1);

        uint32_t w0 = sb + S_W + (uint32_t)s0 * SLOT_BYTES;   // h0: n 0..47
        uint32_t w1 = sb + S_W + (uint32_t)s1 * SLOT_BYTES;   // h1: n 48..87
        uint32_t abase_p = a_base + (uint32_t)p * (2*XPITCH);

        #pragma unroll
        for (int kk = 0; kk < 11; kk++) {
            uint32_t a0[4], a1[4];
            ldmatrix_x4(a0[0], a0[1], a0[2], a0[3], abase_p + kk*32);
            ldmatrix_x4(a1[0], a1[1], a1[2], a1[3], abase_p + 16*XPITCH + kk*32);
            // h0: n-tiles 0..5
            #pragma unroll
            for (int jp = 0; jp < 3; jp++) {
                uint32_t b0, b1, b2, b3;
                ldmatrix_x4(b0, b1, b2, b3, w0 + b_lane + (uint32_t)jp*16*WP2 + kk*32);
                mma16816(acc[0][2*jp],   a0[0], a0[1], a0[2], a0[3], b0, b1);
                mma16816(acc[1][2*jp],   a1[0], a1[1], a1[2], a1[3], b0, b1);
                mma16816(acc[0][2*jp+1], a0[0], a0[1], a0[2], a0[3], b2, b3);
                mma16816(acc[1][2*jp+1], a1[0], a1[1], a1[2], a1[3], b2, b3);
            }
            // h1: n-tiles 6..9
            #pragma unroll
            for (int jp = 0; jp < 2; jp++) {
                uint32_t b0, b1, b2, b3;
                ldmatrix_x4(b0, b1, b2, b3, w1 + b_lane + (uint32_t)jp*16*WP2 + kk*32);
                mma16816(acc[0][6+2*jp], a0[0], a0[1], a0[2], a0[3], b0, b1);
                mma16816(acc[1][6+2*jp], a1[0], a1[1], a1[2], a1[3], b0, b1);
                mma16816(acc[0][7+2*jp], a0[0], a0[1], a0[2], a0[3], b2, b3);
                mma16816(acc[1][7+2*jp], a1[0], a1[1], a1[2], a1[3], b2, b3);
            }
            // h1: n-tile 10
            {
                uint32_t b0, b1;
                ldmatrix_x2(b0, b1, w1 + b_lane2 + kk*32);
                mma16816(acc[0][10], a0[0], a0[1], a0[2], a0[3], b0, b1);
                mma16816(acc[1][10], a1[0], a1[1], a1[2], a1[3], b0, b1);
            }
        }

        __syncthreads();
        // reload: s0 <- q=2p+3 (odd, H1 bytes), s1 <- q=2p+4 (even, full bytes)
        if (tid == 0) {
            int qa = 2*p + 3;
            if (qa < 64) {
                MBARRIER_EXPECT_TX(mb_w + s0*8, H1_BYTES);
                bulk_g2s(sb + S_W + (uint32_t)s0*SLOT_BYTES,
                         (const void*)(g_Wimg + (size_t)qa*SLOT_BYTES), H1_BYTES, mb_w + s0*8);
            }
            int qb = 2*p + 4;
            if (qb < 64) {
                MBARRIER_EXPECT_TX(mb_w + s1*8, SLOT_BYTES);
                bulk_g2s(sb + S_W + (uint32_t)s1*SLOT_BYTES,
                         (const void*)(g_Wimg + (size_t)qb*SLOT_BYTES), SLOT_BYTES, mb_w + s1*8);
            }
        }
        wpar ^= (1u << s0);
        wpar ^= (1u << s1);
        slot = (slot + 2 >= NSLOTS) ? slot + 2 - NSLOTS : slot + 2;
    }

    // ---- epilogue: add bias, store twice ----
    {
        int col0 = (lane & 3) * 2;          // within n-tile
        int rbase = t0 + wid * ROWS_PER_WARP + (lane >> 2);
        #pragma unroll
        for (int mt = 0; mt < 2; mt++) {
            int r0 = rbase + mt * 16;
            size_t g0 = ((size_t)n_b * TT + r0)     * FF;
            size_t g1 = ((size_t)n_b * TT + r0 + 8) * FF;
            #pragma unroll
            for (int j = 0; j < 11; j++) {
                int c = j * 8 + col0;
                float bx = bias[c], by = bias[c + 1];
                float2 v0 = make_float2(acc[mt][j][0] + bx, acc[mt][j][1] + by);
                float2 v1 = make_float2(acc[mt][j][2] + bx, acc[mt][j][3] + by);
                *(float2*)(out + g0 + c) = v0;
                *(float2*)(out + g1 + c) = v1;
                *(float2*)(out + OUT_HALF + g0 + c) = v0;
                *(float2*)(out + OUT_HALF + g1 + c) = v1;
            }
        }
    }
}

// ---------------------------------------------------------------------------
// Launch
// ---------------------------------------------------------------------------
extern "C" void kernel_launch(void* const* d_in, const int* in_sizes, int n_in,
                              void* d_out, int out_size) {
    const float *x = nullptr, *W = nullptr, *b = nullptr;
    for (int i = 0; i < n_in; i++) {
        if      (in_sizes[i] == X_ELEMS) x = (const float*)d_in[i];
        else if (in_sizes[i] == W_ELEMS) W = (const float*)d_in[i];
        else if (in_sizes[i] == FF)      b = (const float*)d_in[i];
    }
    cudaFuncSetAttribute(main_gemm_kernel,
                         cudaFuncAttributeMaxDynamicSharedMemorySize, SMEM_ALLOC);
    prep_w_kernel<<<(PREP_W_ITEMS + 255)/256, 256>>>(W);
    main_gemm_kernel<<<NB*(TT/TILE_T), 256, SMEM_ALLOC>>>(x, b, (float*)d_out);
}